// round 3
// baseline (speedup 1.0000x reference)
#include <cuda_runtime.h>
#include <cuda_bf16.h>

#define TICKS 10000
#define S_BINS 9
#define OUT_CH 64
#define R_REP 32
#define PLANE (S_BINS * TICKS)      // 90000
#define T4 (TICKS / 4)              // 2500

// Replicated classification histograms + final suffix-summed buffer.
__device__ __align__(16) float g_GR[R_REP * PLANE];   // 11.5 MB
__device__ __align__(16) float g_BUF[PLANE];

// ---------------------------------------------------------------------------
// K1: zero scratch (float4-vectorized).
// ---------------------------------------------------------------------------
__global__ void k_zero() {
    const int idx = blockIdx.x * blockDim.x + threadIdx.x;
    const int gr4 = (R_REP * PLANE) / 4;   // 720000
    const int b4  = PLANE / 4;             // 22500
    float4 z = make_float4(0.f, 0.f, 0.f, 0.f);
    if (idx < gr4) reinterpret_cast<float4*>(g_GR)[idx] = z;
    if (idx < b4)  reinterpret_cast<float4*>(g_BUF)[idx] = z;
}

// ---------------------------------------------------------------------------
// K2: event scatter with 32-way replica spreading.
//   stride==1: 1 atomicAdd/event into g_GR[r][bin][t], bin = min(y,2)*3+min(x,2)
//   fallback : 9 checked atomicAdds into g_BUF directly
// 4 events/thread via vectorized loads; replica = global warp id & 31.
// ---------------------------------------------------------------------------
__global__ void k_scatter(const float* __restrict__ vals,
                          const int*   __restrict__ ticks,
                          const int*   __restrict__ xs,
                          const int*   __restrict__ ys,
                          const int*   __restrict__ stride_p,
                          int n) {
    const int st  = *stride_p;
    const int tid = blockIdx.x * blockDim.x + threadIdx.x;
    const int rep = (tid >> 5) & (R_REP - 1);
    float* __restrict__ G = g_GR + rep * PLANE;
    const int base = tid * 4;

    if (base + 3 < n) {
        float4 v4 = *reinterpret_cast<const float4*>(vals  + base);
        int4   t4 = *reinterpret_cast<const int4*>  (ticks + base);
        int4   x4 = *reinterpret_cast<const int4*>  (xs    + base);
        int4   y4 = *reinterpret_cast<const int4*>  (ys    + base);

        float v[4] = {v4.x, v4.y, v4.z, v4.w};
        int   t[4] = {t4.x, t4.y, t4.z, t4.w};
        int   x[4] = {x4.x, x4.y, x4.z, x4.w};
        int   y[4] = {y4.x, y4.y, y4.z, y4.w};

        if (st == 1) {
            #pragma unroll
            for (int i = 0; i < 4; i++) {
                int cx = x[i] < 2 ? x[i] : 2;
                int cy = y[i] < 2 ? y[i] : 2;
                atomicAdd(&G[(cy * 3 + cx) * TICKS + t[i]], v[i]);
            }
        } else {
            #pragma unroll
            for (int i = 0; i < 4; i++) {
                #pragma unroll
                for (int ky = 0; ky < 3; ky++) {
                    #pragma unroll
                    for (int kx = 0; kx < 3; kx++) {
                        int ox = x[i] - kx, oy = y[i] - ky;
                        if (ox >= 0 && oy >= 0 && (ox % st) == 0 && (oy % st) == 0)
                            atomicAdd(&g_BUF[(ky * 3 + kx) * TICKS + t[i]], v[i]);
                    }
                }
            }
        }
    } else if (base < n) {
        for (int i = base; i < n; i++) {
            float v = vals[i];
            int   t = ticks[i], x = xs[i], y = ys[i];
            if (st == 1) {
                int cx = x < 2 ? x : 2;
                int cy = y < 2 ? y : 2;
                atomicAdd(&G[(cy * 3 + cx) * TICKS + t], v);
            } else {
                for (int ky = 0; ky < 3; ky++)
                    for (int kx = 0; kx < 3; kx++) {
                        int ox = x - kx, oy = y - ky;
                        if (ox >= 0 && oy >= 0 && (ox % st) == 0 && (oy % st) == 0)
                            atomicAdd(&g_BUF[(ky * 3 + kx) * TICKS + t], v);
                    }
            }
        }
    }
}

// ---------------------------------------------------------------------------
// K3: reduce 32 replicas + 3x3 2D suffix sum:
//   BUF[ky*3+kx][t] = sum_{cy>=ky, cx>=kx} sum_r GR[r][cy*3+cx][t]
// No-op for stride != 1 (BUF already holds the final answer).
// ---------------------------------------------------------------------------
__global__ void k_suffix(const int* __restrict__ stride_p) {
    if (*stride_p != 1) return;
    int t = blockIdx.x * blockDim.x + threadIdx.x;
    if (t >= TICKS) return;

    float g[9];
    #pragma unroll
    for (int b = 0; b < 9; b++) g[b] = 0.f;
    #pragma unroll
    for (int r = 0; r < R_REP; r++) {
        const float* G = g_GR + r * PLANE;
        #pragma unroll
        for (int b = 0; b < 9; b++) g[b] += G[b * TICKS + t];
    }

    // suffix over cx within each cy row
    #pragma unroll
    for (int cy = 0; cy < 3; cy++) {
        g[cy * 3 + 1] += g[cy * 3 + 2];
        g[cy * 3 + 0] += g[cy * 3 + 1];
    }
    // suffix over cy within each kx column
    #pragma unroll
    for (int kx = 0; kx < 3; kx++) {
        g[1 * 3 + kx] += g[2 * 3 + kx];
        g[0 * 3 + kx] += g[1 * 3 + kx];
    }

    #pragma unroll
    for (int b = 0; b < 9; b++) g_BUF[b * TICKS + t] = g[b];
}

// ---------------------------------------------------------------------------
// K4: broadcast BUF[9][T] to out[64][9][T].
// grid = (ceil(T4/128), 9, 16); each thread reads one float4 of BUF and
// writes it into 4 channels. 360K threads, pure store-bound (~23MB).
// ---------------------------------------------------------------------------
__global__ void k_broadcast(float4* __restrict__ out) {
    int col = blockIdx.x * blockDim.x + threadIdx.x;   // 0..T4-1
    if (col >= T4) return;
    int s      = blockIdx.y;                            // 0..8
    int cgroup = blockIdx.z;                            // 0..15 -> channels 4*z..4*z+3
    float4 v = reinterpret_cast<const float4*>(g_BUF)[s * T4 + col];
    float4* dst = out + (cgroup * 4) * (S_BINS * T4) + s * T4 + col;
    #pragma unroll
    for (int c = 0; c < 4; c++)
        dst[c * (S_BINS * T4)] = v;
}

// ---------------------------------------------------------------------------
extern "C" void kernel_launch(void* const* d_in, const int* in_sizes, int n_in,
                              void* d_out, int out_size) {
    const float* vals    = (const float*)d_in[0];
    const int*   ticks   = (const int*)  d_in[1];
    const int*   xs      = (const int*)  d_in[2];
    const int*   ys      = (const int*)  d_in[3];
    const int*   stridep = (const int*)  d_in[4];
    int n = in_sizes[0];

    // K1: zero scratch
    {
        int total = (R_REP * PLANE) / 4;
        k_zero<<<(total + 255) / 256, 256>>>();
    }
    // K2: scatter, 4 events/thread
    {
        int threads = (n + 3) / 4;
        k_scatter<<<(threads + 255) / 256, 256>>>(vals, ticks, xs, ys, stridep, n);
    }
    // K3: replica-reduce + suffix sum
    k_suffix<<<(TICKS + 255) / 256, 256>>>(stridep);

    // K4: broadcast to all 64 channels
    {
        dim3 grid((T4 + 127) / 128, S_BINS, 16);
        k_broadcast<<<grid, 128>>>((float4*)d_out);
    }
}

// round 4
// speedup vs baseline: 1.0956x; 1.0956x over previous
#include <cuda_runtime.h>
#include <cuda_bf16.h>
#include <cstdint>

#define TICKS 10000
#define S_BINS 9
#define OUT_CH 64
#define PLANE (S_BINS * TICKS)      // 90000
#define T4 (TICKS / 4)              // 2500

#define NB    296                   // scatter blocks (2 per SM)
#define BTH   512                   // scatter block threads
#define R_RARE 8                    // replicas for rare-bin global atomics

// Scratch:
__device__ __align__(16) float g_HOT[NB * TICKS];        // per-block hot (bin 8) histograms, 11.8 MB
__device__ __align__(16) float g_G[R_RARE * PLANE];      // rare-bin replicated histograms, 2.9 MB
__device__ __align__(16) float g_BUF[PLANE];             // final suffix-summed buffer

// ---------------------------------------------------------------------------
// K1: zero g_G and g_BUF (g_HOT is fully overwritten by the flush).
// ---------------------------------------------------------------------------
__global__ void k_zero() {
    const int idx = blockIdx.x * blockDim.x + threadIdx.x;
    const int g4 = (R_RARE * PLANE) / 4;   // 180000
    const int b4 = PLANE / 4;              // 22500
    float4 z = make_float4(0.f, 0.f, 0.f, 0.f);
    if (idx < g4) reinterpret_cast<float4*>(g_G)[idx] = z;
    if (idx < b4) reinterpret_cast<float4*>(g_BUF)[idx] = z;
}

// ---------------------------------------------------------------------------
// K2: two-phase scatter (stride==1 fast path):
//   hot events (x>=2 && y>=2, ~97%): atomicAdd into 40KB SMEM tick histogram
//   rare events: global atomicAdd into g_G[blockIdx&7][bin][t]
//   flush: SMEM histogram -> g_HOT[blockIdx][*] with plain float4 stores.
// stride!=1 fallback: 9 validity-checked global atomicAdds into g_BUF.
// ---------------------------------------------------------------------------
__global__ void __launch_bounds__(BTH, 2) k_scatter(
        const float* __restrict__ vals,
        const int*   __restrict__ ticks,
        const int*   __restrict__ xs,
        const int*   __restrict__ ys,
        const int*   __restrict__ stride_p,
        int n) {
    __shared__ __align__(16) float hist[TICKS];

    const int st  = *stride_p;
    const int b   = blockIdx.x;
    const int tid = threadIdx.x;

    const int per_block = (((n + NB - 1) / NB) + 3) & ~3;   // multiple of 4
    const int start = b * per_block;
    const int end   = min(n, start + per_block);
    if (start >= n) return;

    if (st == 1) {
        // zero SMEM histogram
        #pragma unroll
        for (int i = tid; i < T4; i += BTH)
            reinterpret_cast<float4*>(hist)[i] = make_float4(0.f, 0.f, 0.f, 0.f);
        __syncthreads();

        float* __restrict__ Grare = g_G + (b & (R_RARE - 1)) * PLANE;

        const int vec_end = start + ((end - start) & ~3);
        for (int i = start + tid * 4; i + 3 < vec_end + 4 && i + 3 < end + 4 && i + 3 < vec_end ? 0 : (i + 3 < vec_end); ) { break; }  // (placeholder removed below)

        for (int i = start + tid * 4; i + 3 < vec_end; i += BTH * 4) {
            float4 v4 = *reinterpret_cast<const float4*>(vals  + i);
            int4   t4 = *reinterpret_cast<const int4*>  (ticks + i);
            int4   x4 = *reinterpret_cast<const int4*>  (xs    + i);
            int4   y4 = *reinterpret_cast<const int4*>  (ys    + i);
            float v[4] = {v4.x, v4.y, v4.z, v4.w};
            int   t[4] = {t4.x, t4.y, t4.z, t4.w};
            int   x[4] = {x4.x, x4.y, x4.z, x4.w};
            int   y[4] = {y4.x, y4.y, y4.z, y4.w};
            #pragma unroll
            for (int e = 0; e < 4; e++) {
                if (x[e] >= 2 && y[e] >= 2) {
                    atomicAdd(&hist[t[e]], v[e]);
                } else {
                    int cx = x[e] < 2 ? x[e] : 2;
                    int cy = y[e] < 2 ? y[e] : 2;
                    atomicAdd(&Grare[(cy * 3 + cx) * TICKS + t[e]], v[e]);
                }
            }
        }
        // ragged tail (last block only)
        for (int i = vec_end + tid; i < end; i += BTH) {
            float v = vals[i];
            int t = ticks[i], x = xs[i], y = ys[i];
            if (x >= 2 && y >= 2) {
                atomicAdd(&hist[t], v);
            } else {
                int cx = x < 2 ? x : 2;
                int cy = y < 2 ? y : 2;
                atomicAdd(&Grare[(cy * 3 + cx) * TICKS + t], v);
            }
        }

        __syncthreads();
        // flush SMEM histogram to per-block global slot (plain stores)
        float4* dst = reinterpret_cast<float4*>(g_HOT + b * TICKS);
        #pragma unroll
        for (int i = tid; i < T4; i += BTH)
            dst[i] = reinterpret_cast<const float4*>(hist)[i];
    } else {
        // generic stride fallback: direct checked atomics into g_BUF
        for (int i = start + tid; i < end; i += BTH) {
            float v = vals[i];
            int t = ticks[i], x = xs[i], y = ys[i];
            #pragma unroll
            for (int ky = 0; ky < 3; ky++)
                #pragma unroll
                for (int kx = 0; kx < 3; kx++) {
                    int ox = x - kx, oy = y - ky;
                    if (ox >= 0 && oy >= 0 && (ox % st) == 0 && (oy % st) == 0)
                        atomicAdd(&g_BUF[(ky * 3 + kx) * TICKS + t], v);
                }
        }
    }
}

// ---------------------------------------------------------------------------
// K3: reduce hot slices + rare replicas, then 3x3 2D suffix sum.
//   g[8] (cy=2,cx=2) gets the hot sum; bins 0-7 come from g_G replicas.
// No-op for stride != 1 (g_BUF already final).
// ---------------------------------------------------------------------------
__global__ void k_suffix(const int* __restrict__ stride_p) {
    if (*stride_p != 1) return;
    int t = blockIdx.x * blockDim.x + threadIdx.x;
    if (t >= TICKS) return;

    float g[9];
    #pragma unroll
    for (int bn = 0; bn < 9; bn++) g[bn] = 0.f;

    #pragma unroll
    for (int r = 0; r < R_RARE; r++) {
        const float* G = g_G + r * PLANE;
        #pragma unroll
        for (int bn = 0; bn < 9; bn++) g[bn] += G[bn * TICKS + t];
    }
    float hot = 0.f;
    for (int b = 0; b < NB; b++) hot += g_HOT[b * TICKS + t];
    g[8] += hot;

    // suffix over cx within each cy row
    #pragma unroll
    for (int cy = 0; cy < 3; cy++) {
        g[cy * 3 + 1] += g[cy * 3 + 2];
        g[cy * 3 + 0] += g[cy * 3 + 1];
    }
    // suffix over cy within each kx column
    #pragma unroll
    for (int kx = 0; kx < 3; kx++) {
        g[1 * 3 + kx] += g[2 * 3 + kx];
        g[0 * 3 + kx] += g[1 * 3 + kx];
    }

    #pragma unroll
    for (int bn = 0; bn < 9; bn++) g_BUF[bn * TICKS + t] = g[bn];
}

// ---------------------------------------------------------------------------
// K4: broadcast BUF[9][T] -> out[64][9][T] via bulk async SMEM->GMEM copies.
// grid = 36 blocks: s = blk>>2, quarter q = blk&3 (2500 floats = 10KB slice).
// Block stages the slice in SMEM, then 64 threads each bulk-copy it to one
// output channel.
// ---------------------------------------------------------------------------
__global__ void k_broadcast(float* __restrict__ out) {
    __shared__ __align__(16) float tile[TICKS / 4];   // 2500 floats = 10KB
    const int s = blockIdx.x >> 2;
    const int q = blockIdx.x & 3;
    const int slice = TICKS / 4;                      // 2500 floats

    const float4* src = reinterpret_cast<const float4*>(g_BUF + s * TICKS + q * slice);
    for (int i = threadIdx.x; i < slice / 4; i += blockDim.x)
        reinterpret_cast<float4*>(tile)[i] = src[i];
    __syncthreads();
    asm volatile("fence.proxy.async.shared::cta;" ::: "memory");

    if (threadIdx.x < OUT_CH) {
        uint32_t saddr;
        asm("{ .reg .u64 tmp; cvta.to.shared.u64 tmp, %1; cvt.u32.u64 %0, tmp; }"
            : "=r"(saddr) : "l"(tile));
        float* dst = out + threadIdx.x * PLANE + s * TICKS + q * slice;
        unsigned bytes = slice * 4;                   // 10000, multiple of 16
        asm volatile("cp.async.bulk.global.shared::cta.bulk_group [%0], [%1], %2;"
                     :: "l"(dst), "r"(saddr), "r"(bytes) : "memory");
        asm volatile("cp.async.bulk.commit_group;" ::: "memory");
        asm volatile("cp.async.bulk.wait_group 0;" ::: "memory");
    }
}

// ---------------------------------------------------------------------------
extern "C" void kernel_launch(void* const* d_in, const int* in_sizes, int n_in,
                              void* d_out, int out_size) {
    const float* vals    = (const float*)d_in[0];
    const int*   ticks   = (const int*)  d_in[1];
    const int*   xs      = (const int*)  d_in[2];
    const int*   ys      = (const int*)  d_in[3];
    const int*   stridep = (const int*)  d_in[4];
    int n = in_sizes[0];

    // K1: zero rare + final buffers
    {
        int total = (R_RARE * PLANE) / 4;
        k_zero<<<(total + 255) / 256, 256>>>();
    }
    // K2: two-phase scatter
    k_scatter<<<NB, BTH>>>(vals, ticks, xs, ys, stridep, n);

    // K3: reduce + suffix sum
    k_suffix<<<(TICKS + 255) / 256, 256>>>(stridep);

    // K4: bulk-copy broadcast to 64 channels
    k_broadcast<<<S_BINS * 4, 256>>>((float*)d_out);
}